// round 10
// baseline (speedup 1.0000x reference)
#include <cuda_runtime.h>
#include <cstdint>

// SpecAugment: time-warp (±W shifted gather, zero borders) + freq mask + time mask.
// B=128, M=80, T=3000, W=80.
// Persistent grid-stride version of the R4 shape: grid = 148 SMs x 8 blocks
// (one full wave at 256 thr / 32 regs), each block loops over rows. Removes
// the 9-wave launch structure (8 wave transitions + 65%-full tail) and hoists
// scalar params out of the per-row path. Plain stores (.cs measured worse),
// float4 loads, load-skip for fully time-masked groups.

namespace {
constexpr int B = 128;
constexpr int M = 80;
constexpr int T = 3000;
constexpr int W = 80;
constexpr int V = T / 4;            // 750 float4 groups per row
constexpr int THREADS = 256;
constexpr int K = 3;                // groups per thread (768 >= 750)
constexpr int NROWS = B * M;        // 10240
constexpr int GRID = 148 * 8;       // one-wave persistent fill
}

__global__ void __launch_bounds__(THREADS)
specaug_kernel(const float* __restrict__ spec,
               const int*   __restrict__ centers,
               const int*   __restrict__ fs_p,
               const int*   __restrict__ fw_p,
               const int*   __restrict__ ts_p,
               const int*   __restrict__ tw_p,
               float*       __restrict__ out)
{
    // per-block scalars, loaded once
    const int f_start = __ldg(fs_p);
    const int f_end   = f_start + __ldg(fw_p);
    const int t_start = __ldg(ts_p);
    const int t_end   = t_start + __ldg(tw_p);

    // per-thread group ids / time offsets, invariant across rows
    int vg[K], tg[K];
    #pragma unroll
    for (int k = 0; k < K; k++) {
        vg[k] = threadIdx.x + k * THREADS;
        tg[k] = vg[k] * 4;
    }

    for (int bm = blockIdx.x; bm < NROWS; bm += GRID) {
        const int b = bm / M;
        const int m = bm - b * M;

        float4* __restrict__ orow = reinterpret_cast<float4*>(out) + (size_t)bm * V;

        // ---- frequency mask: whole row zero -> write-only path (no reads)
        if (m >= f_start && m < f_end) {
            const float4 z = make_float4(0.f, 0.f, 0.f, 0.f);
            #pragma unroll
            for (int k = 0; k < K; k++)
                if (vg[k] < V) orow[vg[k]] = z;
            continue;
        }

        const int c = __ldg(centers + b);
        const float* __restrict__ row = spec + (size_t)bm * T;

        // ---- phase 1: 3 independent float4 gathers, branch-free common path.
        // tg and W are multiples of 4 -> shifted loads stay 16B aligned; the
        // zero-border regions cover whole groups. Fully time-masked groups
        // skip their load (zeroed anyway).
        float4 vals[K];
        #pragma unroll
        for (int k = 0; k < K; k++) {
            const int t0  = tg[k];
            const int idx = (t0 + 4 <= c) ? (t0 - W) : (t0 + W);
            const bool masked = (t0 >= t_start) && (t0 + 4 <= t_end);
            const bool ok = (vg[k] < V) && (idx >= 0) && (idx + 4 <= T) && !masked;
            vals[k] = ok ? *reinterpret_cast<const float4*>(row + idx)
                         : make_float4(0.f, 0.f, 0.f, 0.f);
        }

        // ---- phase 2: straddle fixup (<=1 group per row), time mask, store
        #pragma unroll
        for (int k = 0; k < K; k++) {
            if (vg[k] >= V) break;
            const int t0 = tg[k];
            float4 val = vals[k];
            float* vp = reinterpret_cast<float*>(&val);

            if (t0 < c && c < t0 + 4) {              // group straddles the center
                #pragma unroll
                for (int j = 0; j < 4; j++) {
                    const int t   = t0 + j;
                    const int idx = (t < c) ? (t - W) : (t + W);
                    vp[j] = (idx >= 0 && idx < T) ? __ldg(row + idx) : 0.f;
                }
            }

            if (t0 + 4 > t_start && t0 < t_end) {    // group touches the mask band
                #pragma unroll
                for (int j = 0; j < 4; j++) {
                    const int t = t0 + j;
                    if (t >= t_start && t < t_end) vp[j] = 0.f;
                }
            }

            orow[vg[k]] = val;
        }
    }
}

extern "C" void kernel_launch(void* const* d_in, const int* in_sizes, int n_in,
                              void* d_out, int out_size)
{
    const float* spec    = (const float*)d_in[0];
    const int*   centers = (const int*)  d_in[1];
    const int*   f_start = (const int*)  d_in[2];
    const int*   f_width = (const int*)  d_in[3];
    const int*   t_start = (const int*)  d_in[4];
    const int*   t_width = (const int*)  d_in[5];
    float*       out     = (float*)      d_out;

    specaug_kernel<<<GRID, THREADS>>>(spec, centers, f_start, f_width,
                                      t_start, t_width, out);
}